// round 7
// baseline (speedup 1.0000x reference)
#include <cuda_runtime.h>
#include <cuda_bf16.h>
#include <cstdint>

#define CHARS 128
#define CE    64
#define HE    128
#define GE    512
#define WE    256
#define HP    256
#define GP    1024
#define KIN   384
#define TAGS  50
#define NW    8192
#define MAXC  16

__device__ float g_table[CHARS * GE];
__device__ float g_hchar[NW * HE];
__device__ float g_xgp[NW * GP];
__device__ float g_hs[NW * HP];

__device__ __forceinline__ float sigmf(float x) { return 1.0f / (1.0f + __expf(-x)); }

// ---- K1: per-char-id input projection table + biases ----
__global__ void k_table(const float* __restrict__ ce_emb, const float* __restrict__ Wih,
                        const float* __restrict__ bih, const float* __restrict__ bhh) {
    __shared__ float ce[CE];
    int c = blockIdx.x;
    if (threadIdx.x < CE) ce[threadIdx.x] = ce_emb[c * CE + threadIdx.x];
    __syncthreads();
    int g = threadIdx.x;
    float acc = bih[g] + bhh[g];
    const float* wr = Wih + g * CE;
#pragma unroll
    for (int k = 0; k < CE; k++) acc += ce[k] * wr[k];
    g_table[c * GE + g] = acc;
}

// ---- K2: batched char LSTM, 16 words/block ----
#define K2S 520
__global__ __launch_bounds__(256) void k_char(const float* __restrict__ Whh,
                                              const int* __restrict__ char_ids,
                                              const int* __restrict__ char_len) {
    extern __shared__ float sm[];
    float* w_tile = sm;                  // 32 x K2S
    float* h_s = sm + 32 * K2S;          // 16 x 128
    int* cid_s = (int*)(h_s + 16 * HE);  // 16
    int* len_s = cid_s + 16;             // 16

    int tid = threadIdx.x;
    int tc = tid & 63;
    int tw = tid >> 6;
    int w0 = blockIdx.x * 16;

    for (int i = tid; i < 16 * HE; i += 256) h_s[i] = 0.0f;
    if (tid < 16) len_s[tid] = char_len[w0 + tid];

    float cc[4][2];
#pragma unroll
    for (int i = 0; i < 4; i++) { cc[i][0] = 0.f; cc[i][1] = 0.f; }
    __syncthreads();

    for (int t = 0; t < MAXC; t++) {
        float acc[4][2][4];
#pragma unroll
        for (int a = 0; a < 4; a++)
#pragma unroll
            for (int b = 0; b < 2; b++)
#pragma unroll
                for (int d = 0; d < 4; d++) acc[a][b][d] = 0.f;

        for (int ch = 0; ch < 4; ch++) {
            int k0 = ch * 32;
            __syncthreads();
            for (int idx = tid; idx < GE * 32; idx += 256) {
                int g = idx >> 5, kk = idx & 31;
                w_tile[kk * K2S + g] = Whh[g * HE + k0 + kk];
            }
            if (ch == 0 && tid < 16) cid_s[tid] = char_ids[(w0 + tid) * MAXC + t];
            __syncthreads();
            for (int kk = 0; kk < 32; kk++) {
                float hv[4];
#pragma unroll
                for (int i = 0; i < 4; i++) hv[i] = h_s[(tw * 4 + i) * HE + k0 + kk];
                const float* wr = w_tile + kk * K2S;
#pragma unroll
                for (int tau = 0; tau < 4; tau++) {
                    float2 wv = *(const float2*)(wr + tau * HE + tc * 2);
#pragma unroll
                    for (int i = 0; i < 4; i++) {
                        acc[tau][0][i] += hv[i] * wv.x;
                        acc[tau][1][i] += hv[i] * wv.y;
                    }
                }
            }
        }
        __syncthreads();
#pragma unroll
        for (int i = 0; i < 4; i++) {
            int w = tw * 4 + i;
            if (t < len_s[w]) {
                const float* tr = g_table + cid_s[w] * GE;
#pragma unroll
                for (int j = 0; j < 2; j++) {
                    int jj = tc * 2 + j;
                    float gi = acc[0][j][i] + tr[jj];
                    float gf = acc[1][j][i] + tr[HE + jj];
                    float gg = acc[2][j][i] + tr[2 * HE + jj];
                    float go = acc[3][j][i] + tr[3 * HE + jj];
                    float cn = sigmf(gf) * cc[i][j] + sigmf(gi) * tanhf(gg);
                    cc[i][j] = cn;
                    h_s[w * HE + jj] = sigmf(go) * tanhf(cn);
                }
            }
        }
    }
#pragma unroll
    for (int i = 0; i < 4; i++) {
        int w = tw * 4 + i;
#pragma unroll
        for (int j = 0; j < 2; j++)
            g_hchar[(w0 + w) * HE + tc * 2 + j] = h_s[w * HE + tc * 2 + j];
    }
}

// ---- K3: word-LSTM input projection GEMM [8192,384]x[384,1024] ----
__global__ __launch_bounds__(256) void k_feat(const float* __restrict__ word_emb,
                                              const float* __restrict__ Wih,
                                              const float* __restrict__ bih,
                                              const float* __restrict__ bhh,
                                              const int* __restrict__ sentence) {
    __shared__ float a_tile[16 * 33];
    __shared__ float w_tile[32 * 264];
    __shared__ int sent_s[16];

    int tid = threadIdx.x;
    int tg = tid & 63;
    int tn = tid >> 6;
    int n0 = blockIdx.x * 16;
    int g0 = blockIdx.y * 256;

    if (tid < 16) sent_s[tid] = sentence[n0 + tid];

    float acc[4][4];
#pragma unroll
    for (int i = 0; i < 4; i++)
#pragma unroll
        for (int j = 0; j < 4; j++) acc[i][j] = 0.f;

    for (int kc = 0; kc < 12; kc++) {
        int k0 = kc * 32;
        __syncthreads();
        int idx = tid;
#pragma unroll
        for (int rep = 0; rep < 2; rep++, idx += 256) {
            int n = idx >> 5, kk = idx & 31;
            int k = k0 + kk;
            float v;
            if (k < WE) v = word_emb[(size_t)sent_s[n] * WE + k];
            else v = g_hchar[(n0 + n) * HE + (k - WE)];
            a_tile[n * 33 + kk] = v;
        }
        for (int j = tid; j < 256 * 32; j += 256) {
            int g = j >> 5, kk = j & 31;
            w_tile[kk * 264 + g] = Wih[(size_t)(g0 + g) * KIN + k0 + kk];
        }
        __syncthreads();
        for (int kk = 0; kk < 32; kk++) {
            float4 wv = *(const float4*)(w_tile + kk * 264 + tg * 4);
            float av[4];
#pragma unroll
            for (int i = 0; i < 4; i++) av[i] = a_tile[(tn * 4 + i) * 33 + kk];
#pragma unroll
            for (int i = 0; i < 4; i++) {
                acc[i][0] += av[i] * wv.x;
                acc[i][1] += av[i] * wv.y;
                acc[i][2] += av[i] * wv.z;
                acc[i][3] += av[i] * wv.w;
            }
        }
    }
    float bias[4];
#pragma unroll
    for (int j = 0; j < 4; j++) {
        int gg = g0 + tg * 4 + j;
        bias[j] = bih[gg] + bhh[gg];
    }
#pragma unroll
    for (int i = 0; i < 4; i++) {
        int n = n0 + tn * 4 + i;
        float4 o;
        o.x = acc[i][0] + bias[0];
        o.y = acc[i][1] + bias[1];
        o.z = acc[i][2] + bias[2];
        o.w = acc[i][3] + bias[3];
        *(float4*)(g_xgp + (size_t)n * GP + g0 + tg * 4) = o;
    }
}

// ---- K4: sequential word LSTM, 8-CTA cluster, Whh in registers ----
__global__ void __cluster_dims__(8, 1, 1) __launch_bounds__(256, 1)
k_word(const float* __restrict__ Whh, int N) {
    __shared__ __align__(16) float h_s[2][HP];
    __shared__ float gbuf[128];

    int tid = threadIdx.x;
    int r = blockIdx.x;
    int row = tid >> 1;
    int half = tid & 1;
    int tau = row >> 5;
    int jj = row & 31;
    int g = tau * HP + r * 32 + jj;

    float w[128];
    const float4* wp = (const float4*)(Whh + (size_t)g * HP + half * 128);
#pragma unroll
    for (int i = 0; i < 32; i++) {
        float4 v = wp[i];
        w[4 * i] = v.x; w[4 * i + 1] = v.y; w[4 * i + 2] = v.z; w[4 * i + 3] = v.w;
    }
    for (int i = tid; i < 2 * HP; i += 256) (&h_s[0][0])[i] = 0.f;
    float c = 0.f;
    __syncthreads();
    asm volatile("barrier.cluster.arrive.aligned;\n\tbarrier.cluster.wait.aligned;" ::: "memory");

    for (int n = 0; n < N; n++) {
        int cur = n & 1;
        float xgv = 0.f;
        if (half == 0) xgv = __ldg(&g_xgp[(size_t)n * GP + g]);

        const float4* hp = (const float4*)(&h_s[cur][half * 128]);
        float a0 = 0.f, a1 = 0.f, a2 = 0.f, a3 = 0.f;
#pragma unroll
        for (int i = 0; i < 32; i++) {
            float4 hv = hp[i];
            a0 += w[4 * i] * hv.x;
            a1 += w[4 * i + 1] * hv.y;
            a2 += w[4 * i + 2] * hv.z;
            a3 += w[4 * i + 3] * hv.w;
        }
        float v = (a0 + a1) + (a2 + a3);
        v += __shfl_down_sync(0xffffffffu, v, 1);
        if (half == 0) gbuf[row] = v + xgv;
        __syncthreads();

        if (tid < 32) {
            float gi = gbuf[tid], gf = gbuf[32 + tid], gg = gbuf[64 + tid], go = gbuf[96 + tid];
            float cn = sigmf(gf) * c + sigmf(gi) * tanhf(gg);
            c = cn;
            float hv = sigmf(go) * tanhf(cn);
            int u = r * 32 + tid;
            int nxt = cur ^ 1;
            h_s[nxt][u] = hv;
            g_hs[(size_t)n * HP + u] = hv;
            uint32_t laddr = (uint32_t)__cvta_generic_to_shared(&h_s[nxt][u]);
#pragma unroll
            for (int pr = 0; pr < 8; pr++) {
                if (pr != r) {
                    uint32_t ra;
                    asm volatile("mapa.shared::cluster.u32 %0, %1, %2;" : "=r"(ra) : "r"(laddr), "r"(pr));
                    asm volatile("st.shared::cluster.f32 [%0], %1;" :: "r"(ra), "f"(hv) : "memory");
                }
            }
        }
        asm volatile("barrier.cluster.arrive.aligned;\n\tbarrier.cluster.wait.aligned;" ::: "memory");
    }
}

// ---- K5: tag projection + log_softmax ----
__global__ __launch_bounds__(256) void k_tag(const float* __restrict__ Wt,
                                             const float* __restrict__ bt_g,
                                             float* __restrict__ out) {
    extern __shared__ float sm2[];
    float* wt = sm2;                 // 50 * 257
    float* hrow = wt + TAGS * 257;   // 32 * 256
    float* lg = hrow + 32 * HP;      // 32 * 52
    float* bt = lg + 32 * 52;        // 50
    float* lse_s = bt + TAGS;        // 32

    int tid = threadIdx.x;
    int r0 = blockIdx.x * 32;

    for (int i = tid; i < TAGS * HP; i += 256) {
        int t = i / HP, k = i - t * HP;
        wt[t * 257 + k] = Wt[i];
    }
    for (int i = tid; i < 32 * HP; i += 256) hrow[i] = g_hs[(size_t)r0 * HP + i];
    if (tid < TAGS) bt[tid] = bt_g[tid];
    __syncthreads();

    for (int idx = tid; idx < 32 * TAGS; idx += 256) {
        int rr = idx / TAGS, t = idx - rr * TAGS;
        float a = bt[t];
        const float* hh = hrow + rr * HP;
        const float* ww = wt + t * 257;
#pragma unroll 8
        for (int k = 0; k < HP; k++) a += hh[k] * ww[k];
        lg[rr * 52 + t] = a;
    }
    __syncthreads();
    if (tid < 32) {
        float mx = -1e30f;
        for (int t = 0; t < TAGS; t++) mx = fmaxf(mx, lg[tid * 52 + t]);
        float s = 0.f;
        for (int t = 0; t < TAGS; t++) s += __expf(lg[tid * 52 + t] - mx);
        lse_s[tid] = mx + logf(s);
    }
    __syncthreads();
    for (int idx = tid; idx < 32 * TAGS; idx += 256) {
        int rr = idx / TAGS, t = idx - rr * TAGS;
        out[(size_t)(r0 + rr) * TAGS + t] = lg[rr * 52 + t] - lse_s[rr];
    }
}

extern "C" void kernel_launch(void* const* d_in, const int* in_sizes, int n_in,
                              void* d_out, int out_size) {
    const float* char_emb = (const float*)d_in[0];
    const float* word_emb = (const float*)d_in[1];
    const float* Wih_e = (const float*)d_in[2];
    const float* Whh_e = (const float*)d_in[3];
    const float* bih_e = (const float*)d_in[4];
    const float* bhh_e = (const float*)d_in[5];
    const float* Wih_p = (const float*)d_in[6];
    const float* Whh_p = (const float*)d_in[7];
    const float* bih_p = (const float*)d_in[8];
    const float* bhh_p = (const float*)d_in[9];
    const float* W_tag = (const float*)d_in[10];
    const float* b_tag = (const float*)d_in[11];
    const int* sentence = (const int*)d_in[12];
    const int* char_ids = (const int*)d_in[13];
    const int* char_lengths = (const int*)d_in[14];
    float* out = (float*)d_out;

    // idempotent, host-side only (not captured as graph nodes)
    cudaFuncSetAttribute(k_char, cudaFuncAttributeMaxDynamicSharedMemorySize,
                         (32 * K2S + 16 * HE) * 4 + 32 * 4);
    cudaFuncSetAttribute(k_tag, cudaFuncAttributeMaxDynamicSharedMemorySize,
                         (TAGS * 257 + 32 * HP + 32 * 52 + TAGS + 32) * 4);

    k_table<<<CHARS, GE>>>(char_emb, Wih_e, bih_e, bhh_e);
    k_char<<<NW / 16, 256, (32 * K2S + 16 * HE) * 4 + 32 * 4>>>(Whh_e, char_ids, char_lengths);
    dim3 fg(NW / 16, GP / 256);
    k_feat<<<fg, 256>>>(word_emb, Wih_p, bih_p, bhh_p, sentence);
    k_word<<<8, 256>>>(Whh_p, NW);
    k_tag<<<NW / 32, 256, (TAGS * 257 + 32 * HP + 32 * 52 + TAGS + 32) * 4>>>(W_tag, b_tag, out);
}